// round 3
// baseline (speedup 1.0000x reference)
#include <cuda_runtime.h>

#define DD     64
#define NUSERS 100000
#define NENT   100000
#define NNODES 200000
#define EKG    1500000
#define EPREF  1500000
#define NNZK   1000000

// Scratch (no allocations allowed) — ~180 MB of device globals.
__device__ float g_entA[(size_t)NENT * DD];
__device__ float g_entB[(size_t)NENT * DD];
__device__ float g_nodeA[(size_t)NNODES * DD];
__device__ float g_nodeB[(size_t)NNODES * DD];
__device__ float g_uacc[(size_t)NUSERS * DD];
__device__ int   g_cntE[NENT];
__device__ int   g_cntN[NNODES];

// ---------------------------------------------------------------------------
// KG edges: out[head] += ent[tail] * weight[etype-1]; cnt[head] += 1
// 16 threads per edge, one float4 each (coalesced 256B row gather + RED.v4).
// ---------------------------------------------------------------------------
__global__ __launch_bounds__(256) void kg_scatter_k(
    const float* __restrict__ ent, const int* __restrict__ head,
    const int* __restrict__ tail, const int* __restrict__ etype,
    const float* __restrict__ w, float* __restrict__ out, int* __restrict__ cnt)
{
    unsigned tid = blockIdx.x * 256u + threadIdx.x;
    if (tid >= (unsigned)EKG * 16u) return;
    unsigned e = tid >> 4, c = tid & 15u;
    int h = head[e], t = tail[e], r = etype[e] - 1;
    float4 v  = reinterpret_cast<const float4*>(ent + (size_t)t * DD)[c];
    float4 ww = reinterpret_cast<const float4*>(w + (size_t)r * DD)[c];
    v.x *= ww.x; v.y *= ww.y; v.z *= ww.z; v.w *= ww.w;
    atomicAdd(reinterpret_cast<float4*>(out + (size_t)h * DD) + c, v);
    if (c == 0) atomicAdd(cnt + h, 1);
}

// ---------------------------------------------------------------------------
// Preference edges: src row comes from user-part (node table) or entity table.
// ---------------------------------------------------------------------------
__global__ __launch_bounds__(256) void pref_scatter_k(
    const float* __restrict__ userpart, const float* __restrict__ entpart,
    const int* __restrict__ ehead, const int* __restrict__ etail,
    const int* __restrict__ etype, const float* __restrict__ w,
    float* __restrict__ out, int* __restrict__ cnt)
{
    unsigned tid = blockIdx.x * 256u + threadIdx.x;
    if (tid >= (unsigned)EPREF * 16u) return;
    unsigned e = tid >> 4, c = tid & 15u;
    int h = ehead[e], t = etail[e], r = etype[e];
    const float* src = (t < NUSERS) ? (userpart + (size_t)t * DD)
                                    : (entpart + (size_t)(t - NUSERS) * DD);
    float4 v  = reinterpret_cast<const float4*>(src)[c];
    float4 ww = reinterpret_cast<const float4*>(w + (size_t)r * DD)[c];
    v.x *= ww.x; v.y *= ww.y; v.z *= ww.z; v.w *= ww.w;
    atomicAdd(reinterpret_cast<float4*>(out + (size_t)h * DD) + c, v);
    if (c == 0) atomicAdd(cnt + h, 1);
}

// ---------------------------------------------------------------------------
// Divide entity sums by counts (mean), in place. Must run BEFORE interact.
// ---------------------------------------------------------------------------
__global__ __launch_bounds__(256) void ent_mean_k(
    float* __restrict__ buf, const int* __restrict__ cnt)
{
    unsigned tid = blockIdx.x * 256u + threadIdx.x;
    if (tid >= (unsigned)NENT * 16u) return;
    unsigned row = tid >> 4, c = tid & 15u;
    float inv = 1.f / fmaxf((float)cnt[row], 1.f);
    float4* p = reinterpret_cast<float4*>(buf + (size_t)row * DD) + c;
    float4 v = *p;
    v.x *= inv; v.y *= inv; v.z *= inv; v.w *= inv;
    *p = v;
}

// ---------------------------------------------------------------------------
// Interact: uacc[rows] += vals * ent_mean[cols]
// ---------------------------------------------------------------------------
__global__ __launch_bounds__(256) void interact_k(
    const float* __restrict__ ent, const int* __restrict__ rows,
    const int* __restrict__ cols, const float* __restrict__ vals,
    float* __restrict__ uacc)
{
    unsigned tid = blockIdx.x * 256u + threadIdx.x;
    if (tid >= (unsigned)NNZK * 16u) return;
    unsigned e = tid >> 4, c = tid & 15u;
    int r = rows[e], col = cols[e];
    float s = vals[e];
    float4 v = reinterpret_cast<const float4*>(ent + (size_t)col * DD)[c];
    v.x *= s; v.y *= s; v.z *= s; v.w *= s;
    atomicAdd(reinterpret_cast<float4*>(uacc + (size_t)r * DD) + c, v);
}

// ---------------------------------------------------------------------------
// Fused finalize: optional mean divide, L2-normalize in place,
// optional residual add (res += v), optional copy-out.
// One warp per row (32 lanes x float2).
// ---------------------------------------------------------------------------
__global__ __launch_bounds__(256) void finalize_k(
    float* __restrict__ buf, const int* __restrict__ cnt,
    float* __restrict__ res, float* __restrict__ copyout, int nrows)
{
    int row = blockIdx.x * 8 + (int)(threadIdx.x >> 5);
    if (row >= nrows) return;
    int lane = threadIdx.x & 31;
    float2* p = reinterpret_cast<float2*>(buf + (size_t)row * DD) + lane;
    float2 v = *p;
    if (cnt) {
        float inv = 1.f / fmaxf((float)cnt[row], 1.f);
        v.x *= inv; v.y *= inv;
    }
    float ss = v.x * v.x + v.y * v.y;
    #pragma unroll
    for (int o = 16; o > 0; o >>= 1) ss += __shfl_xor_sync(0xffffffffu, ss, o);
    float inv = 1.f / fmaxf(sqrtf(ss), 1e-12f);
    v.x *= inv; v.y *= inv;
    *p = v;
    if (res) {
        float2* q = reinterpret_cast<float2*>(res + (size_t)row * DD) + lane;
        float2 r = *q; r.x += v.x; r.y += v.y; *q = r;
    }
    if (copyout)
        reinterpret_cast<float2*>(copyout + (size_t)row * DD)[lane] = v;
}

// ---------------------------------------------------------------------------
extern "C" void kernel_launch(void* const* d_in, const int* in_sizes, int n_in,
                              void* d_out, int out_size)
{
    (void)in_sizes; (void)n_in; (void)out_size;
    const float* user_emb   = (const float*)d_in[0];
    const float* entity_emb = (const float*)d_in[1];
    const float* weight     = (const float*)d_in[2];
    const float* exweight   = (const float*)d_in[3];
    const float* ivals      = (const float*)d_in[4];
    const int*   eidx       = (const int*)d_in[5];
    const int*   etype      = (const int*)d_in[6];
    const int*   xeidx      = (const int*)d_in[7];
    const int*   xetype     = (const int*)d_in[8];
    const int*   iidx       = (const int*)d_in[9];
    float* out = (float*)d_out;

    const int* head  = eidx;
    const int* tail  = eidx + EKG;
    const int* ehead = xeidx;
    const int* etail = xeidx + EPREF;
    const int* rows  = iidx;
    const int* cols  = iidx + NNZK;

    float *entA, *entB, *nodeA, *nodeB, *uacc;
    int *cntE, *cntN;
    cudaGetSymbolAddress((void**)&entA,  g_entA);
    cudaGetSymbolAddress((void**)&entB,  g_entB);
    cudaGetSymbolAddress((void**)&nodeA, g_nodeA);
    cudaGetSymbolAddress((void**)&nodeB, g_nodeB);
    cudaGetSymbolAddress((void**)&uacc,  g_uacc);
    cudaGetSymbolAddress((void**)&cntE,  g_cntE);
    cudaGetSymbolAddress((void**)&cntN,  g_cntN);

    // Output layout: gcn_res = [user_res ; ent_final], then node_res.
    float* user_res = out;                                   // NUSERS*DD
    float* ent_out  = out + (size_t)NUSERS * DD;             // NENT*DD
    float* node_res = out + (size_t)(NUSERS + NENT) * DD;    // NNODES*DD

    // Residual initialization (fully rewrites all d_out regions each replay).
    cudaMemcpyAsync(user_res, user_emb, sizeof(float) * (size_t)NUSERS * DD,
                    cudaMemcpyDeviceToDevice);
    cudaMemcpyAsync(node_res, user_emb, sizeof(float) * (size_t)NUSERS * DD,
                    cudaMemcpyDeviceToDevice);
    cudaMemcpyAsync(node_res + (size_t)NUSERS * DD, entity_emb,
                    sizeof(float) * (size_t)NENT * DD, cudaMemcpyDeviceToDevice);

    const float* entCur   = entity_emb;  // entity table read this hop
    const float* userPart = user_emb;    // user slice of node table read this hop
    float* entNext  = entA;
    float* nodeNext = nodeA;

    const int B = 256;
    for (int hop = 0; hop < 2; hop++) {
        cudaMemsetAsync(entNext,  0, sizeof(float) * (size_t)NENT * DD);
        cudaMemsetAsync(nodeNext, 0, sizeof(float) * (size_t)NNODES * DD);
        cudaMemsetAsync(uacc,     0, sizeof(float) * (size_t)NUSERS * DD);
        cudaMemsetAsync(cntE,     0, sizeof(int) * NENT);
        cudaMemsetAsync(cntN,     0, sizeof(int) * NNODES);

        kg_scatter_k<<<(EKG * 16 + B - 1) / B, B>>>(
            entCur, head, tail, etype, weight, entNext, cntE);
        pref_scatter_k<<<(EPREF * 16 + B - 1) / B, B>>>(
            userPart, entCur, ehead, etail, xetype, exweight, nodeNext, cntN);
        ent_mean_k<<<(NENT * 16 + B - 1) / B, B>>>(entNext, cntE);
        interact_k<<<(NNZK * 16 + B - 1) / B, B>>>(entNext, rows, cols, ivals, uacc);

        // entity: normalize (mean already applied); last hop also writes output
        finalize_k<<<(NENT + 7) / 8, B>>>(
            entNext, nullptr, nullptr, (hop == 1) ? ent_out : nullptr, NENT);
        // node: mean + normalize + residual into node_res
        finalize_k<<<(NNODES + 7) / 8, B>>>(
            nodeNext, cntN, node_res, nullptr, NNODES);
        // user: normalize + residual into user_res
        finalize_k<<<(NUSERS + 7) / 8, B>>>(
            uacc, nullptr, user_res, nullptr, NUSERS);

        entCur   = entNext;
        userPart = nodeNext;   // next hop's user slice = normalized node table
        entNext  = entB;
        nodeNext = nodeB;
    }
}